// round 2
// baseline (speedup 1.0000x reference)
#include <cuda_runtime.h>

// GAE: g[t] = delta[t] + (gamma*lam*nd[t]) * g[t+1]   (reverse-time scan)
// delta[t] = r[t] + gamma*nv[t]*nd[t] - v[t]
// Chunked parallel scan over T: pass1 (local P,S) -> pass2 (cross-chunk scan)
// -> pass3 (replay with correct incoming state, write adv & returns).
//
// NOTE: next_dones (jax bool) is materialized by the harness as int32.

#define T_STEPS 4096
#define NENV    2048
#define NCHUNK  64
#define CHUNK   (T_STEPS / NCHUNK)   // 64

__device__ float g_P[NCHUNK * NENV];  // product of coefficients per chunk
__device__ float g_S[NCHUNK * NENV];  // local scan value (incoming state = 0)
__device__ float g_G[NCHUNK * NENV];  // incoming state for each chunk

__device__ __forceinline__ constexpr float GAMMA_F() { return 0.99f; }
__device__ __forceinline__ constexpr float GD_F()    { return 0.99f * 0.95f; }

// ---------------------------------------------------------------------------
// Pass 1: each (chunk, env) thread runs the recurrence locally with g_in = 0,
// accumulating S (local value at chunk start) and P (product of a[t]).
// ---------------------------------------------------------------------------
__global__ void __launch_bounds__(256) gae_pass1(
    const float* __restrict__ rewards,
    const float* __restrict__ values,
    const float* __restrict__ next_values,
    const int*   __restrict__ next_dones)
{
    const int e = blockIdx.x * blockDim.x + threadIdx.x;   // env index
    const int c = blockIdx.y;                              // chunk index

    float g = 0.0f;
    float p = 1.0f;
    const int base = ((c + 1) * CHUNK - 1) * NENV + e;     // last timestep of chunk

    #pragma unroll 8
    for (int t = 0; t < CHUNK; t++) {
        const int idx = base - t * NENV;
        const float nd    = next_dones[idx] ? 0.0f : 1.0f;
        const float a     = GD_F() * nd;
        const float delta = rewards[idx] + GAMMA_F() * next_values[idx] * nd - values[idx];
        g = delta + a * g;
        p *= a;
    }
    g_P[c * NENV + e] = p;
    g_S[c * NENV + e] = g;
}

// ---------------------------------------------------------------------------
// Pass 2: per-env sequential scan over the 64 chunks (reverse time).
// G[c] = state entering chunk c from the later side.
// ---------------------------------------------------------------------------
__global__ void __launch_bounds__(256) gae_pass2()
{
    const int e = blockIdx.x * blockDim.x + threadIdx.x;   // env index
    float g = 0.0f;
    #pragma unroll
    for (int c = NCHUNK - 1; c >= 0; c--) {
        g_G[c * NENV + e] = g;
        g = g_S[c * NENV + e] + g_P[c * NENV + e] * g;
    }
}

// ---------------------------------------------------------------------------
// Pass 3: replay each chunk with the correct incoming state; write outputs.
// ---------------------------------------------------------------------------
__global__ void __launch_bounds__(256) gae_pass3(
    const float* __restrict__ rewards,
    const float* __restrict__ values,
    const float* __restrict__ next_values,
    const int*   __restrict__ next_dones,
    float* __restrict__ adv,
    float* __restrict__ ret)
{
    const int e = blockIdx.x * blockDim.x + threadIdx.x;   // env index
    const int c = blockIdx.y;                              // chunk index

    float g = g_G[c * NENV + e];
    const int base = ((c + 1) * CHUNK - 1) * NENV + e;

    #pragma unroll 8
    for (int t = 0; t < CHUNK; t++) {
        const int idx = base - t * NENV;
        const float nd    = next_dones[idx] ? 0.0f : 1.0f;
        const float vv    = values[idx];
        const float delta = rewards[idx] + GAMMA_F() * next_values[idx] * nd - vv;
        g = delta + GD_F() * nd * g;
        adv[idx] = g;
        ret[idx] = g + vv;
    }
}

// ---------------------------------------------------------------------------
// Launch
// ---------------------------------------------------------------------------
extern "C" void kernel_launch(void* const* d_in, const int* in_sizes, int n_in,
                              void* d_out, int out_size)
{
    const float* rewards     = (const float*)d_in[0];
    const float* values      = (const float*)d_in[1];
    const float* next_values = (const float*)d_in[2];
    const int*   next_dones  = (const int*)d_in[3];

    float* adv = (float*)d_out;                            // first T*N elements
    float* ret = (float*)d_out + (size_t)T_STEPS * NENV;   // second T*N elements

    dim3 block(256);
    dim3 grid1(NENV / 256, NCHUNK);   // (8, 64) = 512 blocks

    gae_pass1<<<grid1, block>>>(rewards, values, next_values, next_dones);
    gae_pass2<<<NENV / 256, block>>>();
    gae_pass3<<<grid1, block>>>(rewards, values, next_values, next_dones, adv, ret);
}

// round 3
// speedup vs baseline: 1.0749x; 1.0749x over previous
#include <cuda_runtime.h>

// GAE chunked parallel scan, minimum-traffic version.
// g[t] = delta[t] + a[t]*g[t+1],  a[t] = gd*nd[t],  delta = r + gamma*nv*nd - v
//
// Pass1: per (chunk,env) local backward scan with g_in=0.
//        Writes adv_scratch = S_t and ret_scratch = S_t + v_t IN-PLACE into d_out,
//        plus a cumulative-nodone bitmask and per-chunk (P,S).
//        Inputs read with __ldcs (streaming) -> scratch stays L2-resident.
// Pass2: tiny per-env scan over chunks -> incoming state G per chunk.
// Pass3: fix-up: fix = bit[t] * gd^(dist+1) * G ; adv += fix ; ret += fix.
//        Pure L2-hot read-modify-write of d_out. No input re-read.

#define T_STEPS 4096
#define NENV    2048
#define NCHUNK  128
#define CHUNK   (T_STEPS / NCHUNK)   // 32

__device__ float        g_P[NCHUNK * NENV];   // full-chunk coefficient product
__device__ float        g_S[NCHUNK * NENV];   // chunk-local scan value at chunk start
__device__ float        g_G[NCHUNK * NENV];   // incoming state per chunk
__device__ unsigned int g_bits[NCHUNK * NENV]; // bit t' = nodone over suffix [tt..chunk_end]

__device__ __forceinline__ constexpr float GAMMA_F() { return 0.99f; }
__device__ __forceinline__ constexpr float GD_F()    { return 0.99f * 0.95f; }

// ---------------------------------------------------------------------------
// Pass 1
// ---------------------------------------------------------------------------
__global__ void __launch_bounds__(256) gae_pass1(
    const float* __restrict__ rewards,
    const float* __restrict__ values,
    const float* __restrict__ next_values,
    const int*   __restrict__ next_dones,
    float* __restrict__ adv_s,    // d_out first half  (scratch: S_t)
    float* __restrict__ ret_s)    // d_out second half (scratch: S_t + v)
{
    const int e = blockIdx.x * blockDim.x + threadIdx.x;   // env
    const int c = blockIdx.y;                              // time chunk
    const int base = ((c + 1) * CHUNK - 1) * NENV + e;     // last timestep of chunk

    float g = 0.0f;
    float p = 1.0f;
    unsigned int bits = 0u;
    bool alive = true;   // cumulative nodone over the suffix

    #pragma unroll 8
    for (int t = 0; t < CHUNK; t++) {          // t=0 is the LAST timestep (backward)
        const int idx = base - t * NENV;
        const int   d  = __ldcs(&next_dones[idx]);
        const float r  = __ldcs(&rewards[idx]);
        const float nv = __ldcs(&next_values[idx]);
        const float v  = __ldcs(&values[idx]);

        const float nd    = d ? 0.0f : 1.0f;
        const float a     = GD_F() * nd;
        const float delta = r + GAMMA_F() * nv * nd - v;
        g = delta + a * g;
        p *= a;
        alive = alive && (d == 0);
        if (alive) bits |= (1u << t);

        adv_s[idx] = g;          // S_t  (local adv, zero incoming state)
        ret_s[idx] = g + v;      // S_t + v
    }

    const int o = c * NENV + e;
    g_P[o] = p;
    g_S[o] = g;
    g_bits[o] = bits;
}

// ---------------------------------------------------------------------------
// Pass 2: per-env reverse scan over the NCHUNK chunk summaries.
// ---------------------------------------------------------------------------
__global__ void __launch_bounds__(256) gae_pass2()
{
    const int e = blockIdx.x * blockDim.x + threadIdx.x;
    float g = 0.0f;
    #pragma unroll 8
    for (int c = NCHUNK - 1; c >= 0; c--) {
        const int o = c * NENV + e;
        g_G[o] = g;                       // state entering chunk c (from later time)
        g = g_S[o] + g_P[o] * g;
    }
}

// ---------------------------------------------------------------------------
// Pass 3: fix-up. adv[t] = S_t + pp_t*G ; ret[t] = (S_t+v) + pp_t*G
// pp_t = gd^(t+1) * bit(t)   with t = distance from chunk end (0-based).
// ---------------------------------------------------------------------------
__global__ void __launch_bounds__(256) gae_pass3(
    float* __restrict__ adv,
    float* __restrict__ ret)
{
    const int e = blockIdx.x * blockDim.x + threadIdx.x;
    const int c = blockIdx.y;
    const int o = c * NENV + e;
    const int base = ((c + 1) * CHUNK - 1) * NENV + e;

    const float        G    = g_G[o];
    const unsigned int bits = g_bits[o];

    float pw = GD_F();
    #pragma unroll 8
    for (int t = 0; t < CHUNK; t++) {
        const int idx = base - t * NENV;
        const float fix = ((bits >> t) & 1u) ? pw * G : 0.0f;
        adv[idx] += fix;
        ret[idx] += fix;
        pw *= GD_F();
    }
}

// ---------------------------------------------------------------------------
// Launch
// ---------------------------------------------------------------------------
extern "C" void kernel_launch(void* const* d_in, const int* in_sizes, int n_in,
                              void* d_out, int out_size)
{
    const float* rewards     = (const float*)d_in[0];
    const float* values      = (const float*)d_in[1];
    const float* next_values = (const float*)d_in[2];
    const int*   next_dones  = (const int*)d_in[3];

    float* adv = (float*)d_out;
    float* ret = (float*)d_out + (size_t)T_STEPS * NENV;

    dim3 block(256);
    dim3 grid1(NENV / 256, NCHUNK);   // (8, 128) = 1024 blocks

    gae_pass1<<<grid1, block>>>(rewards, values, next_values, next_dones, adv, ret);
    gae_pass2<<<NENV / 256, block>>>();
    gae_pass3<<<grid1, block>>>(adv, ret);
}

// round 4
// speedup vs baseline: 1.5115x; 1.4062x over previous
#include <cuda_runtime.h>

// GAE chunked parallel scan, v4.
// Pass1 (x2-vectorized): local backward scan per (chunk, env-pair), writes
//   scratch adv_s/ret_s into d_out, summary (P,S) as float2, nodone bitmask.
// Pass2 (register-prefetched): per-env scan over 128 chunk summaries.
// Pass3 (x2-vectorized): L2-hot RMW fixup of d_out.

#define T_STEPS 4096
#define NENV    2048
#define NCHUNK  128
#define CHUNK   (T_STEPS / NCHUNK)   // 32

__device__ float2       g_PS[NCHUNK * NENV];    // (P, S) per chunk,env
__device__ float        g_G[NCHUNK * NENV];     // incoming state per chunk
__device__ unsigned int g_bits[NCHUNK * NENV];  // suffix-nodone bitmask

__device__ __forceinline__ constexpr float GAMMA_F() { return 0.99f; }
__device__ __forceinline__ constexpr float GD_F()    { return 0.99f * 0.95f; }

// ---------------------------------------------------------------------------
// Pass 1: thread handles 2 consecutive envs. t=0 is the LAST timestep.
// ---------------------------------------------------------------------------
__global__ void __launch_bounds__(256) gae_pass1(
    const float2* __restrict__ rewards,
    const float2* __restrict__ values,
    const float2* __restrict__ next_values,
    const int2*   __restrict__ next_dones,
    float2* __restrict__ adv_s,
    float2* __restrict__ ret_s)
{
    const int e2 = blockIdx.x * blockDim.x + threadIdx.x;  // env-pair index
    const int c  = blockIdx.y;
    const int base = ((c + 1) * CHUNK - 1) * (NENV / 2) + e2;

    float g0 = 0.f, g1 = 0.f, p0 = 1.f, p1 = 1.f;
    unsigned int b0 = 0u, b1 = 0u;
    bool a0 = true, a1 = true;

    #pragma unroll 8
    for (int t = 0; t < CHUNK; t++) {
        const int idx = base - t * (NENV / 2);
        const int2   d  = __ldcs(&next_dones[idx]);
        const float2 r  = __ldcs(&rewards[idx]);
        const float2 nv = __ldcs(&next_values[idx]);
        const float2 v  = __ldcs(&values[idx]);

        const float nd0 = d.x ? 0.f : 1.f;
        const float nd1 = d.y ? 0.f : 1.f;
        g0 = (r.x + GAMMA_F() * nv.x * nd0 - v.x) + GD_F() * nd0 * g0;
        g1 = (r.y + GAMMA_F() * nv.y * nd1 - v.y) + GD_F() * nd1 * g1;
        p0 *= GD_F() * nd0;
        p1 *= GD_F() * nd1;
        a0 = a0 && (d.x == 0);
        a1 = a1 && (d.y == 0);
        if (a0) b0 |= (1u << t);
        if (a1) b1 |= (1u << t);

        adv_s[idx] = make_float2(g0, g1);
        ret_s[idx] = make_float2(g0 + v.x, g1 + v.y);
    }

    const int o = c * NENV + 2 * e2;
    // two consecutive float2 summaries -> one float4 store
    *(float4*)&g_PS[o] = make_float4(p0, g0, p1, g1);
    *(uint2*)&g_bits[o] = make_uint2(b0, b1);
}

// ---------------------------------------------------------------------------
// Pass 2: per-env reverse scan over chunks; prefetch 16 summaries per tile.
// ---------------------------------------------------------------------------
__global__ void __launch_bounds__(256) gae_pass2()
{
    const int e = blockIdx.x * blockDim.x + threadIdx.x;
    float g = 0.0f;
    #pragma unroll
    for (int tile = NCHUNK / 16 - 1; tile >= 0; tile--) {
        float2 ps[16];
        #pragma unroll
        for (int i = 0; i < 16; i++)
            ps[i] = g_PS[(tile * 16 + i) * NENV + e];
        #pragma unroll
        for (int i = 15; i >= 0; i--) {
            const int o = (tile * 16 + i) * NENV + e;
            g_G[o] = g;                    // state entering chunk (from later time)
            g = ps[i].y + ps[i].x * g;     // S + P*g
        }
    }
}

// ---------------------------------------------------------------------------
// Pass 3: fixup RMW. fix = bit(t) * gd^(t+1) * G, added to adv and ret.
// Thread handles 2 consecutive envs.
// ---------------------------------------------------------------------------
__global__ void __launch_bounds__(256) gae_pass3(
    float2* __restrict__ adv,
    float2* __restrict__ ret)
{
    const int e2 = blockIdx.x * blockDim.x + threadIdx.x;
    const int c  = blockIdx.y;
    const int o  = c * NENV + 2 * e2;
    const int base = ((c + 1) * CHUNK - 1) * (NENV / 2) + e2;

    const float2 G = *(const float2*)&g_G[o];
    const uint2  B = *(const uint2*)&g_bits[o];

    float pw = GD_F();
    #pragma unroll 8
    for (int t = 0; t < CHUNK; t++) {
        const int idx = base - t * (NENV / 2);
        const float f0 = ((B.x >> t) & 1u) ? pw * G.x : 0.0f;
        const float f1 = ((B.y >> t) & 1u) ? pw * G.y : 0.0f;
        float2 a = adv[idx];
        float2 rr = ret[idx];
        a.x += f0;  a.y += f1;
        rr.x += f0; rr.y += f1;
        adv[idx] = a;
        ret[idx] = rr;
        pw *= GD_F();
    }
}

// ---------------------------------------------------------------------------
// Launch
// ---------------------------------------------------------------------------
extern "C" void kernel_launch(void* const* d_in, const int* in_sizes, int n_in,
                              void* d_out, int out_size)
{
    const float2* rewards     = (const float2*)d_in[0];
    const float2* values      = (const float2*)d_in[1];
    const float2* next_values = (const float2*)d_in[2];
    const int2*   next_dones  = (const int2*)d_in[3];

    float2* adv = (float2*)d_out;
    float2* ret = (float2*)((float*)d_out + (size_t)T_STEPS * NENV);

    dim3 block(256);
    dim3 grid1(NENV / 2 / 256, NCHUNK);   // (4, 128) = 512 blocks

    gae_pass1<<<grid1, block>>>(rewards, values, next_values, next_dones, adv, ret);
    gae_pass2<<<NENV / 256, block>>>();
    gae_pass3<<<grid1, block>>>(adv, ret);
}